// round 5
// baseline (speedup 1.0000x reference)
#include <cuda_runtime.h>
#include <cstdint>

// Problem constants
#define BB   4
#define TT   2048
#define NC   4096
#define AA   8
#define SINK_ITERS 20
#define EPS_ 1e-5f

#define TOKCTA 16              // tokens per CTA
#define NCTA   (BB * TT / TOKCTA)   // 512
#define DT     128             // d-tile
#define NTILES (NC / DT)       // 32
#define XSTR   132             // x smem row stride (floats): quad = tok+ds mod 8, 4 lanes/quad
#define PSTR   132             // phi smem row stride

// ---------------- scratch ----------------
__device__ __align__(16) float g_buf[AA * 24 * NC];   // folded phi, TRANSPOSED [a][k][d]

// ---------------- helpers ----------------
typedef unsigned long long ull;
__device__ __forceinline__ void ffma2(ull& d, ull a, ull b) {
    asm("fma.rn.f32x2 %0, %1, %2, %0;" : "+l"(d) : "l"(a), "l"(b));
}
__device__ __forceinline__ void fadd2(ull& d, ull a, ull b) {
    asm("add.rn.f32x2 %0, %1, %2;" : "=l"(d) : "l"(a), "l"(b));
}
__device__ __forceinline__ void unpack2(ull u, float& lo, float& hi) {
    asm("mov.b64 {%0, %1}, %2;" : "=f"(lo), "=f"(hi) : "l"(u));
}
__device__ __forceinline__ void cp16(uint32_t dst, const void* src) {
    asm volatile("cp.async.cg.shared.global [%0], [%1], 16;" :: "r"(dst), "l"(src));
}

// ---------------- kernel 1: fold alpha*w*phi -> g_buf[a][k][d] (transposed) ----------------
__global__ void fold_k(const float* __restrict__ wnorm,
                       const float* __restrict__ ppre, const float* __restrict__ ppost,
                       const float* __restrict__ pres,
                       const float* __restrict__ apre, const float* __restrict__ apost,
                       const float* __restrict__ ares) {
    int ad = blockIdx.x * 128 + threadIdx.x;     // a*4096 + d
    if (ad >= AA * NC) return;
    int a = ad >> 12, d = ad & (NC - 1);
    float wv = wnorm[ad];
    float cp = apre[a] * wv, cq = apost[a] * wv, cr = ares[a] * wv;
    float* dst = g_buf + (size_t)a * 24 * NC + d;
    float4 v;
    v = ((const float4*)ppre)[ad];
    dst[0 * NC] = cp * v.x; dst[1 * NC] = cp * v.y; dst[2 * NC] = cp * v.z; dst[3 * NC] = cp * v.w;
    v = ((const float4*)ppost)[ad];
    dst[4 * NC] = cq * v.x; dst[5 * NC] = cq * v.y; dst[6 * NC] = cq * v.z; dst[7 * NC] = cq * v.w;
#pragma unroll
    for (int q = 0; q < 4; ++q) {
        v = ((const float4*)pres)[(size_t)ad * 4 + q];
        dst[(8 + 4 * q) * NC] = cr * v.x; dst[(9 + 4 * q) * NC] = cr * v.y;
        dst[(10 + 4 * q) * NC] = cr * v.z; dst[(11 + 4 * q) * NC] = cr * v.w;
    }
}

// ---------------- fused kernel: logits + sinkhorn + out ----------------
// 512 CTAs x 16 tokens, 256 threads (8 warps).
// warp w: tq = w&3 (token quad), kh = w>>2 (k half: 12 ks).
// lane: tok4 = lane>>3, ds = lane&7. Thread: token tq*4+tok4, 12 ks, d-slice ds.
// acc[k] = f32x2 over (even,odd) d pairs.
__global__ void __launch_bounds__(256, 2)
fused_k(const float* __restrict__ x, float* __restrict__ out,
        const float* __restrict__ bpre, const float* __restrict__ bpost,
        const float* __restrict__ bres, const int* __restrict__ aidx) {
    __shared__ __align__(16) float xs[2][TOKCTA][XSTR];   // 16.9 KB
    __shared__ __align__(16) float ps[2][24][PSTR];       // 25.3 KB
    __shared__ float red[2][TOKCTA][16];                  // 2 KB
    __shared__ float sW[TOKCTA][16];                      // 1 KB

    const int tid = threadIdx.x;
    const int w = tid >> 5, lane = tid & 31;
    const int tq = w & 3, kh = w >> 2;
    const int tok4 = lane >> 3, ds = lane & 7;
    const int tt = tq * 4 + tok4;                 // local token 0..15
    const int aid = aidx[blockIdx.x >> 7];

    const float* gb = g_buf + (size_t)aid * 24 * NC;
    const float* xc = x + (size_t)blockIdx.x * TOKCTA * NC;

    uint32_t xsb = (uint32_t)__cvta_generic_to_shared(&xs[0][0][0]);
    uint32_t psb = (uint32_t)__cvta_generic_to_shared(&ps[0][0][0]);
    const uint32_t XBUF = TOKCTA * XSTR * 4;      // bytes per x buffer
    const uint32_t PBUF = 24 * PSTR * 4;

    // ---- async copy of one d-tile ----
    auto copy_tile = [&](int tile, int bi) {
        const int d0 = tile * DT;
#pragma unroll
        for (int i = 0; i < 2; ++i) {             // x: 512 float4
            int f = i * 256 + tid;
            int t2 = f >> 5, c4 = f & 31;
            cp16(xsb + bi * XBUF + (t2 * XSTR + c4 * 4) * 4,
                 xc + (size_t)t2 * NC + d0 + c4 * 4);
        }
#pragma unroll
        for (int i = 0; i < 3; ++i) {             // phi: 768 float4
            int f = i * 256 + tid;
            int k = f >> 5, c4 = f & 31;
            cp16(psb + bi * PBUF + (k * PSTR + c4 * 4) * 4,
                 gb + (size_t)k * NC + d0 + c4 * 4);
        }
        asm volatile("cp.async.commit_group;");
    };

    ull acc[12];
#pragma unroll
    for (int k = 0; k < 12; ++k) acc[k] = 0ull;
    ull ssq = 0ull;

    copy_tile(0, 0);

    for (int t = 0; t < NTILES; ++t) {
        if (t + 1 < NTILES) {
            copy_tile(t + 1, (t + 1) & 1);
            asm volatile("cp.async.wait_group 1;");
        } else {
            asm volatile("cp.async.wait_group 0;");
        }
        __syncthreads();

        const float* xrow = &xs[t & 1][tt][0];
        const float* pbas = &ps[t & 1][kh * 12][0];
#pragma unroll
        for (int j = 0; j < 4; ++j) {
            const int off = j * 32 + ds * 4;
            ulonglong2 xv = *(const ulonglong2*)(xrow + off);
            if (kh == 0) { ffma2(ssq, xv.x, xv.x); ffma2(ssq, xv.y, xv.y); }
#pragma unroll
            for (int k = 0; k < 12; ++k) {
                ulonglong2 pv = *(const ulonglong2*)(pbas + k * PSTR + off);
                ffma2(acc[k], xv.x, pv.x);
                ffma2(acc[k], xv.y, pv.y);
            }
        }
        __syncthreads();   // all done with buffer (t&1) before it is refilled
    }

    // ---- reduce over 8 d-slices (lane bits 0..2) ----
#pragma unroll
    for (int k = 0; k < 12; ++k) {
#pragma unroll
        for (int m = 1; m < 8; m <<= 1) {
            ull o = __shfl_xor_sync(0xffffffffu, acc[k], m);
            fadd2(acc[k], acc[k], o);
        }
    }
#pragma unroll
    for (int m = 1; m < 8; m <<= 1) {
        ull o = __shfl_xor_sync(0xffffffffu, ssq, m);
        fadd2(ssq, ssq, o);
    }

    if (ds == 0) {
#pragma unroll
        for (int k = 0; k < 12; ++k) {
            float lo, hi; unpack2(acc[k], lo, hi);
            red[kh][tt][k] = lo + hi;
        }
        if (kh == 0) {
            float lo, hi; unpack2(ssq, lo, hi);
            red[0][tt][12] = lo + hi;
        }
    }
    __syncthreads();

    // ---- per-token sinkhorn (16 threads) ----
    if (tid < TOKCTA) {
        const int tk = tid;
        float a[24];
#pragma unroll
        for (int k = 0; k < 12; ++k) { a[k] = red[0][tk][k]; a[12 + k] = red[1][tk][k]; }
        float rinv = rsqrtf(red[0][tk][12] * (1.0f / 4096.0f) + EPS_);

        float hpre[4], hpost[4];
#pragma unroll
        for (int n = 0; n < 4; ++n)
            hpre[n] = 1.0f / (1.0f + expf(-(a[n] * rinv + bpre[aid * 4 + n])));
#pragma unroll
        for (int n = 0; n < 4; ++n)
            hpost[n] = 2.0f / (1.0f + expf(-(a[4 + n] * rinv + bpost[aid * 4 + n])));

        float m[16];
#pragma unroll
        for (int ij = 0; ij < 16; ++ij)
            m[ij] = expf(a[8 + ij] * rinv + bres[aid * 16 + ij]);

        for (int it = 0; it < SINK_ITERS; ++it) {
#pragma unroll
            for (int i = 0; i < 4; ++i) {
                float r = 1.0f / (m[i * 4] + m[i * 4 + 1] + m[i * 4 + 2] + m[i * 4 + 3]);
                m[i * 4] *= r; m[i * 4 + 1] *= r; m[i * 4 + 2] *= r; m[i * 4 + 3] *= r;
            }
#pragma unroll
            for (int j = 0; j < 4; ++j) {
                float r = 1.0f / (m[j] + m[4 + j] + m[8 + j] + m[12 + j]);
                m[j] *= r; m[4 + j] *= r; m[8 + j] *= r; m[12 + j] *= r;
            }
        }
#pragma unroll
        for (int i = 0; i < 4; ++i)
#pragma unroll
            for (int j = 0; j < 4; ++j)
                sW[tk][i * 4 + j] = m[i * 4 + j] + hpost[i] * hpre[j];
    }
    __syncthreads();

    // ---- phase B: out[token] = W @ x[token] (stream x again, write out) ----
    float* oc = out + (size_t)blockIdx.x * TOKCTA * NC;
#pragma unroll
    for (int tk2 = 0; tk2 < 2; ++tk2) {
        const int tkn = w * 2 + tk2;              // 8 warps x 2 = 16 tokens
        float wv[16];
#pragma unroll
        for (int i = 0; i < 16; ++i) wv[i] = sW[tkn][i];
        const float4* xr = (const float4*)(xc + (size_t)tkn * NC);
        float4* orow = (float4*)(oc + (size_t)tkn * NC);
#pragma unroll 2
        for (int it = 0; it < 8; ++it) {
            const int c = it * 32 + lane;
            float4 x0 = xr[c], x1 = xr[256 + c], x2 = xr[512 + c], x3 = xr[768 + c];
#pragma unroll
            for (int i = 0; i < 4; ++i) {
                float w0 = wv[i * 4], w1 = wv[i * 4 + 1], w2 = wv[i * 4 + 2], w3 = wv[i * 4 + 3];
                float4 o;
                o.x = w0 * x0.x + w1 * x1.x + w2 * x2.x + w3 * x3.x;
                o.y = w0 * x0.y + w1 * x1.y + w2 * x2.y + w3 * x3.y;
                o.z = w0 * x0.z + w1 * x1.z + w2 * x2.z + w3 * x3.z;
                o.w = w0 * x0.w + w1 * x1.w + w2 * x2.w + w3 * x3.w;
                orow[i * 256 + c] = o;
            }
        }
    }
}

// ---------------- launch ----------------
extern "C" void kernel_launch(void* const* d_in, const int* in_sizes, int n_in,
                              void* d_out, int out_size) {
    const float* x     = (const float*)d_in[0];
    const float* wnorm = (const float*)d_in[1];
    const float* ppre  = (const float*)d_in[2];
    const float* ppost = (const float*)d_in[3];
    const float* pres  = (const float*)d_in[4];
    const float* bpre  = (const float*)d_in[5];
    const float* bpost = (const float*)d_in[6];
    const float* bres  = (const float*)d_in[7];
    const float* apre  = (const float*)d_in[8];
    const float* apost = (const float*)d_in[9];
    const float* ares  = (const float*)d_in[10];
    const int*   aidx  = (const int*)d_in[11];
    float* out = (float*)d_out;

    fold_k<<<(AA * NC + 127) / 128, 128>>>(wnorm, ppre, ppost, pres, apre, apost, ares);
    fused_k<<<NCTA, 256>>>(x, out, bpre, bpost, bres, aidx);
}

// round 7
// speedup vs baseline: 1.3849x; 1.3849x over previous
#include <cuda_runtime.h>
#include <cstdint>

// Problem constants
#define BB   4
#define TT   2048
#define NC   4096
#define AA   8
#define SINK_ITERS 20
#define EPS_ 1e-5f

#define TOK    16            // tokens per CTA
#define DT     64            // d-tile
#define KSPLIT 8
#define DPART  (NC / KSPLIT) // 512
#define TILES  (DPART / DT)  // 8
#define XROW   68            // x smem row stride (floats)
#define PROW   28            // phi smem row stride (floats)
#define PARTW  28            // partial row: 24 logits + ssq + pad

#define XT (TOK * XROW)      // 1088 floats
#define PT (DT * PROW)       // 1792 floats
#define BUFF (XT + PT)       // 2880 floats = 11.5 KB; double buffered = 23 KB

// ---------------- scratch ----------------
__device__ __align__(16) float g_buf[AA * NC * 24];                 // folded phi [a][d][24]
__device__ __align__(16) float part_buf[KSPLIT * BB * TT * PARTW];  // 7.3 MB
__device__ __align__(16) float W_buf[BB * TT * 16];

// ---------------- helpers ----------------
typedef unsigned long long ull;
__device__ __forceinline__ void ffma2(ull& d, ull a, ull b) {
    asm("fma.rn.f32x2 %0, %1, %2, %0;" : "+l"(d) : "l"(a), "l"(b));
}
__device__ __forceinline__ void fadd2(ull& d, ull a, ull b) {
    asm("add.rn.f32x2 %0, %1, %2;" : "=l"(d) : "l"(a), "l"(b));
}
__device__ __forceinline__ ull dup2(float v) {
    ull r; asm("mov.b64 %0, {%1, %1};" : "=l"(r) : "f"(v)); return r;
}
__device__ __forceinline__ void unpack2(ull u, float& lo, float& hi) {
    asm("mov.b64 {%0, %1}, %2;" : "=f"(lo), "=f"(hi) : "l"(u));
}
__device__ __forceinline__ void cp16(uint32_t dst, const void* src) {
    asm volatile("cp.async.cg.shared.global [%0], [%1], 16;" :: "r"(dst), "l"(src));
}

// ---------------- kernel 1: fold alpha*w*phi -> g_buf[a][d][24] ----------------
__global__ void fold_k(const float* __restrict__ wnorm,
                       const float* __restrict__ ppre, const float* __restrict__ ppost,
                       const float* __restrict__ pres,
                       const float* __restrict__ apre, const float* __restrict__ apost,
                       const float* __restrict__ ares) {
    int i = blockIdx.x * 128 + threadIdx.x;      // a*4096 + d
    if (i >= AA * NC) return;
    int a = i >> 12;
    float wv = wnorm[i];
    float cp = apre[a] * wv, cq = apost[a] * wv, cr = ares[a] * wv;
    float4* dst = (float4*)(g_buf + (size_t)i * 24);
    float4 v;
    v = ((const float4*)ppre)[i];
    dst[0] = make_float4(cp * v.x, cp * v.y, cp * v.z, cp * v.w);
    v = ((const float4*)ppost)[i];
    dst[1] = make_float4(cq * v.x, cq * v.y, cq * v.z, cq * v.w);
#pragma unroll
    for (int q = 0; q < 4; ++q) {
        v = ((const float4*)pres)[(size_t)i * 4 + q];
        dst[2 + q] = make_float4(cr * v.x, cr * v.y, cr * v.z, cr * v.w);
    }
}

// ---------------- kernel 2: partial logits, high occupancy ----------------
// grid = 4096: blockIdx.x = tt*KSPLIT + ks. 128 threads = 4 warps.
// s = tid&7 (d-slice), tg = (tid>>3)&7 (token pair 2tg,2tg+1), kh = tid>>6 (k half).
// acc[j*6+c]: f32x2 over k-pair (kh*12+2c, +1) for token 2tg+j.
__global__ void __launch_bounds__(128, 6)
logits_k(const float* __restrict__ x, const int* __restrict__ aidx) {
    __shared__ __align__(16) float smem[2][BUFF];

    const int tid = threadIdx.x;
    const int ks = blockIdx.x & (KSPLIT - 1);
    const int tt = blockIdx.x >> 3;              // token tile 0..511
    const int t0 = tt * TOK;
    const int aid = aidx[tt >> 7];
    const int s = tid & 7, tg = (tid >> 3) & 7, kh = tid >> 6;

    const float* xb = x + (size_t)t0 * NC + ks * DPART;
    const float* gb = g_buf + ((size_t)aid * NC + ks * DPART) * 24;

    uint32_t sb = (uint32_t)__cvta_generic_to_shared(&smem[0][0]);

    auto copy_tile = [&](int tile, int bi) {
        const int d0 = tile * DT;
        const uint32_t xbase = sb + bi * (BUFF * 4);
        const uint32_t pbase = xbase + XT * 4;
#pragma unroll
        for (int i = 0; i < 2; ++i) {            // x: 256 float4
            int f = i * 128 + tid;
            int tok = f >> 4, q = f & 15;
            cp16(xbase + (tok * XROW + q * 4) * 4, xb + (size_t)tok * NC + d0 + q * 4);
        }
#pragma unroll
        for (int i = 0; i < 3; ++i) {            // phi: 384 float4
            int f = i * 128 + tid;
            int d = f / 6, c = f - d * 6;
            cp16(pbase + (d * PROW + c * 4) * 4, gb + (size_t)(d0 + d) * 24 + c * 4);
        }
        asm volatile("cp.async.commit_group;");
    };

    ull acc[12];
#pragma unroll
    for (int k = 0; k < 12; ++k) acc[k] = 0ull;
    ull ssqa = 0ull, ssqb = 0ull;

    copy_tile(0, 0);

    for (int t = 0; t < TILES; ++t) {
        if (t + 1 < TILES) {
            copy_tile(t + 1, (t + 1) & 1);
            asm volatile("cp.async.wait_group 1;");
        } else {
            asm volatile("cp.async.wait_group 0;");
        }
        __syncthreads();

        const float* xs = &smem[t & 1][0];
        const float* ps = xs + XT;
        const float* xr0 = xs + (2 * tg) * XROW;
        const float* xr1 = xr0 + XROW;

#pragma unroll
        for (int i = 0; i < 8; ++i) {
            const int dd = i * 8 + s;
            ull xa = dup2(xr0[dd]);
            ull xbv = dup2(xr1[dd]);
            if (kh == 0) { ffma2(ssqa, xa, xa); ffma2(ssqb, xbv, xbv); }
            const ulonglong2* pp = (const ulonglong2*)(ps + dd * PROW + kh * 12);
            ulonglong2 pA = pp[0], pB = pp[1], pC = pp[2];
            ffma2(acc[0], xa, pA.x);  ffma2(acc[6],  xbv, pA.x);
            ffma2(acc[1], xa, pA.y);  ffma2(acc[7],  xbv, pA.y);
            ffma2(acc[2], xa, pB.x);  ffma2(acc[8],  xbv, pB.x);
            ffma2(acc[3], xa, pB.y);  ffma2(acc[9],  xbv, pB.y);
            ffma2(acc[4], xa, pC.x);  ffma2(acc[10], xbv, pC.x);
            ffma2(acc[5], xa, pC.y);  ffma2(acc[11], xbv, pC.y);
        }
        __syncthreads();
    }

    // reduce over the 8 d-slices (lane bits 0..2)
#pragma unroll
    for (int k = 0; k < 12; ++k) {
#pragma unroll
        for (int m = 1; m < 8; m <<= 1) {
            ull o = __shfl_xor_sync(0xffffffffu, acc[k], m);
            fadd2(acc[k], acc[k], o);
        }
    }
    if (kh == 0) {
#pragma unroll
        for (int m = 1; m < 8; m <<= 1) {
            ull o = __shfl_xor_sync(0xffffffffu, ssqa, m);
            fadd2(ssqa, ssqa, o);
            o = __shfl_xor_sync(0xffffffffu, ssqb, m);
            fadd2(ssqb, ssqb, o);
        }
    }

    if (s == 0) {
#pragma unroll
        for (int j = 0; j < 2; ++j) {
            float* pa = part_buf + ((size_t)ks * (BB * TT) + t0 + 2 * tg + j) * PARTW;
#pragma unroll
            for (int c = 0; c < 6; ++c) {
                float lo, hi; unpack2(acc[j * 6 + c], lo, hi);
                pa[kh * 12 + 2 * c]     = lo;
                pa[kh * 12 + 2 * c + 1] = hi;
            }
            if (kh == 0) {
                float lo, hi;
                if (j == 0) { unpack2(ssqa, lo, hi); } else { unpack2(ssqb, lo, hi); }
                pa[24] = lo;   // ssq was accumulated on DUPLICATED lanes: lo == hi == true sum
            }
        }
    }
}

// ---------------- kernel 3: finalize (reduce splits, sinkhorn -> W) ----------------
__global__ void finalize_k(const float* __restrict__ bpre, const float* __restrict__ bpost,
                           const float* __restrict__ bres, const int* __restrict__ aidx) {
    const int t = blockIdx.x * 128 + threadIdx.x;
    const int aid = aidx[t >> 11];

    float a[24];
#pragma unroll
    for (int k = 0; k < 24; ++k) a[k] = 0.0f;
    float ssq = 0.0f;
#pragma unroll
    for (int ks = 0; ks < KSPLIT; ++ks) {
        const float4* p = (const float4*)(part_buf + ((size_t)ks * (BB * TT) + t) * PARTW);
#pragma unroll
        for (int q = 0; q < 6; ++q) {
            float4 v = p[q];
            a[q * 4 + 0] += v.x; a[q * 4 + 1] += v.y;
            a[q * 4 + 2] += v.z; a[q * 4 + 3] += v.w;
        }
        ssq += p[6].x;
    }
    float rinv = rsqrtf(ssq * (1.0f / 4096.0f) + EPS_);

    float hpre[4], hpost[4];
#pragma unroll
    for (int n = 0; n < 4; ++n)
        hpre[n] = 1.0f / (1.0f + expf(-(a[n] * rinv + bpre[aid * 4 + n])));
#pragma unroll
    for (int n = 0; n < 4; ++n)
        hpost[n] = 2.0f / (1.0f + expf(-(a[4 + n] * rinv + bpost[aid * 4 + n])));

    float m[16];
#pragma unroll
    for (int ij = 0; ij < 16; ++ij)
        m[ij] = expf(a[8 + ij] * rinv + bres[aid * 16 + ij]);

    for (int it = 0; it < SINK_ITERS; ++it) {
#pragma unroll
        for (int i = 0; i < 4; ++i) {
            float r = 1.0f / (m[i * 4] + m[i * 4 + 1] + m[i * 4 + 2] + m[i * 4 + 3]);
            m[i * 4] *= r; m[i * 4 + 1] *= r; m[i * 4 + 2] *= r; m[i * 4 + 3] *= r;
        }
#pragma unroll
        for (int j = 0; j < 4; ++j) {
            float r = 1.0f / (m[j] + m[4 + j] + m[8 + j] + m[12 + j]);
            m[j] *= r; m[4 + j] *= r; m[8 + j] *= r; m[12 + j] *= r;
        }
    }

    float4* wd = (float4*)(W_buf + (size_t)t * 16);
#pragma unroll
    for (int i = 0; i < 4; ++i)
        wd[i] = make_float4(m[i * 4 + 0] + hpost[i] * hpre[0],
                            m[i * 4 + 1] + hpost[i] * hpre[1],
                            m[i * 4 + 2] + hpost[i] * hpre[2],
                            m[i * 4 + 3] + hpost[i] * hpre[3]);
}

// ---------------- kernel 4: out[token] = W @ x[token] ----------------
__global__ void out_k(const float* __restrict__ x, float* __restrict__ out) {
    const int token = blockIdx.x;
    __shared__ float sW[16];
    if (threadIdx.x < 16) sW[threadIdx.x] = W_buf[(size_t)token * 16 + threadIdx.x];
    __syncthreads();
    const float4* xr = (const float4*)(x + (size_t)token * NC);
    float4* orow = (float4*)(out + (size_t)token * NC);
    const int c = threadIdx.x;
    float4 xv0 = xr[c], xv1 = xr[256 + c], xv2 = xr[512 + c], xv3 = xr[768 + c];
#pragma unroll
    for (int i = 0; i < 4; ++i) {
        float w0 = sW[i * 4], w1 = sW[i * 4 + 1], w2 = sW[i * 4 + 2], w3 = sW[i * 4 + 3];
        float4 o;
        o.x = w0 * xv0.x + w1 * xv1.x + w2 * xv2.x + w3 * xv3.x;
        o.y = w0 * xv0.y + w1 * xv1.y + w2 * xv2.y + w3 * xv3.y;
        o.z = w0 * xv0.z + w1 * xv1.z + w2 * xv2.z + w3 * xv3.z;
        o.w = w0 * xv0.w + w1 * xv1.w + w2 * xv2.w + w3 * xv3.w;
        orow[i * 256 + c] = o;
    }
}

// ---------------- launch ----------------
extern "C" void kernel_launch(void* const* d_in, const int* in_sizes, int n_in,
                              void* d_out, int out_size) {
    const float* x     = (const float*)d_in[0];
    const float* wnorm = (const float*)d_in[1];
    const float* ppre  = (const float*)d_in[2];
    const float* ppost = (const float*)d_in[3];
    const float* pres  = (const float*)d_in[4];
    const float* bpre  = (const float*)d_in[5];
    const float* bpost = (const float*)d_in[6];
    const float* bres  = (const float*)d_in[7];
    const float* apre  = (const float*)d_in[8];
    const float* apost = (const float*)d_in[9];
    const float* ares  = (const float*)d_in[10];
    const int*   aidx  = (const int*)d_in[11];
    float* out = (float*)d_out;

    fold_k<<<(AA * NC + 127) / 128, 128>>>(wnorm, ppre, ppost, pres, apre, apost, ares);
    logits_k<<<(BB * TT / TOK) * KSPLIT, 128>>>(x, aidx);
    finalize_k<<<BB * TT / 128, 128>>>(bpre, bpost, bres, aidx);
    out_k<<<BB * TT, 256>>>(x, out);
}